// round 10
// baseline (speedup 1.0000x reference)
#include <cuda_runtime.h>

#define BATCH 16384

typedef unsigned long long u64;
typedef unsigned int       u32;

// Scratch (device globals: allocation-free rule)
__device__ float  g_xT[64 * BATCH];     // x transposed [i][b]
__device__ float  g_hT[64 * BATCH];     // layer0 output transposed [o][b]
__device__ float4 g_dup0[4096 * 6];     // layer0 params, duplicated (w,w) pairs
__device__ float4 g_dup1[1024 * 6];     // layer1 params, duplicated pairs
__device__ float  g_b3s0[64];           // sum_i b3 per output o, layer0
__device__ float  g_b3s1[16];           // layer1
__device__ u32    g_ctr0[8];            // work-steal counters, layer0 o-groups
__device__ u32    g_ctr1[2];            // layer1 o-groups

__device__ __forceinline__ u64 fma2(u64 a, u64 b, u64 c) {
    u64 d;
    asm("fma.rn.f32x2 %0, %1, %2, %3;" : "=l"(d) : "l"(a), "l"(b), "l"(c));
    return d;
}
__device__ __forceinline__ u64 pk(float a, float b) {
    return (u64)__float_as_uint(a) | ((u64)__float_as_uint(b) << 32);
}
__device__ __forceinline__ float flo(u64 v) { return __uint_as_float((u32)v); }
__device__ __forceinline__ float fhi(u64 v) { return __uint_as_float((u32)(v >> 32)); }
__device__ __forceinline__ u64 relu2(u64 v) {
    return pk(fmaxf(flo(v), 0.0f), fmaxf(fhi(v), 0.0f));
}

// Fused prep: blocks 0..19 param duplication, blocks 20..29 b3 column sums,
// blocks 30..541 x transpose tiles (32b x 64i), block 542 resets counters.
__global__ __launch_bounds__(256) void prep(
    const float* __restrict__ x,
    const float* __restrict__ l0W1, const float* __restrict__ l0b1,
    const float* __restrict__ l0W2, const float* __restrict__ l0b2,
    const float* __restrict__ l0W3, const float* __restrict__ l0b3,
    const float* __restrict__ l1W1, const float* __restrict__ l1b1,
    const float* __restrict__ l1W2, const float* __restrict__ l1b2,
    const float* __restrict__ l1W3, const float* __restrict__ l1b3)
{
    __shared__ float ts[64 * 33];
    int blk = blockIdx.x, tid = threadIdx.x;

    if (blk < 20) {
        int t = blk * 256 + tid;             // 0..5119
        bool isL0 = t < 4096;
        int n = isL0 ? t : t - 4096;
        const float* W1 = isL0 ? l0W1 : l1W1;
        const float* b1 = isL0 ? l0b1 : l1b1;
        const float* W2 = isL0 ? l0W2 : l1W2;
        const float* b2 = isL0 ? l0b2 : l1b2;
        const float* W3 = isL0 ? l0W3 : l1W3;
        float4* q = (isL0 ? g_dup0 : g_dup1) + (size_t)n * 6;
        float w1a = W1[2*n], w1b = W1[2*n+1];
        float b1a = b1[2*n], b1b = b1[2*n+1];
        float w200 = W2[4*n], w201 = W2[4*n+1], w210 = W2[4*n+2], w211 = W2[4*n+3];
        float b2a = b2[2*n], b2b = b2[2*n+1];
        float w3a = W3[2*n], w3b = W3[2*n+1];
        q[0] = make_float4(w1a, w1a, w1b, w1b);
        q[1] = make_float4(b1a, b1a, b1b, b1b);
        q[2] = make_float4(w200, w200, w201, w201);
        q[3] = make_float4(w210, w210, w211, w211);
        q[4] = make_float4(b2a, b2a, b2b, b2b);
        q[5] = make_float4(w3a, w3a, w3b, w3b);
    } else if (blk < 30) {
        int wg = (blk - 20) * 8 + (tid >> 5);   // 0..79
        int lane = tid & 31;
        bool isL0 = wg < 64;
        int o = isL0 ? wg : wg - 64;
        int OUT = isL0 ? 64 : 16;
        const float* b3 = isL0 ? l0b3 : l1b3;
        float s = b3[lane * OUT + o] + b3[(lane + 32) * OUT + o];
#pragma unroll
        for (int m = 16; m; m >>= 1) s += __shfl_xor_sync(0xffffffffu, s, m);
        if (lane == 0) (isL0 ? g_b3s0 : g_b3s1)[o] = s;
    } else if (blk < 542) {
        // Transpose a 32b x 64i tile of x into g_xT, fully vectorized.
        int B0 = (blk - 30) * 32;
        int brow = tid >> 3, i4 = tid & 7;       // 32 rows, 8 f4-cols
#pragma unroll
        for (int p = 0; p < 2; p++) {
            int c = (p * 8 + i4) * 4;
            float4 v = *(const float4*)&x[(size_t)(B0 + brow) * 64 + c];
            ts[(c + 0) * 33 + brow] = v.x;
            ts[(c + 1) * 33 + brow] = v.y;
            ts[(c + 2) * 33 + brow] = v.z;
            ts[(c + 3) * 33 + brow] = v.w;
        }
        __syncthreads();
#pragma unroll
        for (int p = 0; p < 2; p++) {
            int idx = p * 256 + tid;             // 0..511
            int i = idx >> 3, bq = (idx & 7) * 4;
            float4 w = make_float4(ts[i * 33 + bq],     ts[i * 33 + bq + 1],
                                   ts[i * 33 + bq + 2], ts[i * 33 + bq + 3]);
            *(float4*)&g_xT[(size_t)i * BATCH + B0 + bq] = w;
        }
    } else {
        if (tid < 8)  g_ctr0[tid] = 0;
        if (tid < 2)  g_ctr1[tid] = 0;
    }
}

// Persistent KAN layer with per-o-group work stealing.
// grid = (74, NGRP): o-group og = blockIdx.y, 74 CTAs per group (4/SM total
// with 48KB smem each). CTA stages its group's params once, then steals
// 64-batch strips (256 per group) from g_ctr[og]. Warp ol owns column
// o = og*8+ol; lane = one f32x2 pair. Inner loop: 6 uniform LDS.128 + 1
// coalesced LDG.64 + 8 FFMA2 + 8 FMNMX per (i, 64-batch).
// MODE 0: g_xT -> g_hT (transposed rows). MODE 1: g_hT -> dout [b][OUT].
template <int OUT, int MODE>
__global__ __launch_bounds__(256, 4) void kan_layer(float* __restrict__ dout)
{
    __shared__ float4 sp4[64 * 8 * 6];   // 48KB: [i][ol][6]
    __shared__ u32 snext;

    int tid  = threadIdx.x;
    int lane = tid & 31;
    int ol   = tid >> 5;
    int og   = blockIdx.y;
    int o0   = og * 8;
    int o    = o0 + ol;

    // Stage params: per i, subnets n = i*OUT + o0..+7 are 48 contiguous
    // float4 in g_dup -> flat coalesced copy, 12 float4 per thread.
    const float4* dup = ((MODE == 0) ? g_dup0 : g_dup1);
#pragma unroll
    for (int s = tid; s < 3072; s += 256) {
        int i = s / 48;
        int r = s - i * 48;
        sp4[s] = dup[(size_t)(i * OUT + o0) * 6 + r];
    }

    float s3 = ((MODE == 0) ? g_b3s0 : g_b3s1)[o];
    u32* ctr = (MODE == 0) ? &g_ctr0[og] : &g_ctr1[og];
    const float* src = (MODE == 0) ? g_xT : g_hT;
    const ulonglong2* pb = ((const ulonglong2*)sp4) + ol * 6;

    for (;;) {
        __syncthreads();                 // protects snext (WAR) + first-iter staging
        if (tid == 0) snext = atomicAdd(ctr, 1u);
        __syncthreads();
        u32 strip = snext;
        if (strip >= BATCH / 64) break;

        int b = strip * 64 + lane * 2;
        const float* xr = src + b;
        u64 acc = pk(s3, s3);

#pragma unroll 4
        for (int i = 0; i < 64; i++) {
            const ulonglong2* q = pb + i * 48;
            ulonglong2 p0 = q[0], p1 = q[1], p2 = q[2], p3 = q[3], p4 = q[4], p5 = q[5];
            u64 xv = *(const u64*)(xr + (size_t)i * BATCH);
            u64 r1 = relu2(fma2(p0.x, xv, p1.x));
            u64 r2 = relu2(fma2(p0.y, xv, p1.y));
            u64 ga = relu2(fma2(p2.x, r1, fma2(p2.y, r2, p4.x)));
            u64 gb = relu2(fma2(p3.x, r1, fma2(p3.y, r2, p4.y)));
            acc = fma2(p5.y, gb, fma2(p5.x, ga, acc));
        }

        if (MODE == 0) {
            *(u64*)&g_hT[(size_t)o * BATCH + b] = acc;
        } else {
            dout[(size_t)(b + 0) * OUT + o] = flo(acc);
            dout[(size_t)(b + 1) * OUT + o] = fhi(acc);
        }
    }
}

extern "C" void kernel_launch(void* const* d_in, const int* in_sizes, int n_in,
                              void* d_out, int out_size)
{
    const float* x    = (const float*)d_in[0];
    const float* l0W1 = (const float*)d_in[1];
    const float* l0b1 = (const float*)d_in[2];
    const float* l0W2 = (const float*)d_in[3];
    const float* l0b2 = (const float*)d_in[4];
    const float* l0W3 = (const float*)d_in[5];
    const float* l0b3 = (const float*)d_in[6];
    const float* l1W1 = (const float*)d_in[7];
    const float* l1b1 = (const float*)d_in[8];
    const float* l1W2 = (const float*)d_in[9];
    const float* l1b2 = (const float*)d_in[10];
    const float* l1W3 = (const float*)d_in[11];
    const float* l1b3 = (const float*)d_in[12];
    float* out = (float*)d_out;

    prep<<<543, 256>>>(x, l0W1, l0b1, l0W2, l0b2, l0W3, l0b3,
                          l1W1, l1b1, l1W2, l1b2, l1W3, l1b3);
    kan_layer<64, 0><<<dim3(74, 8), 256>>>(nullptr);   // 592 CTAs, 4/SM
    kan_layer<16, 1><<<dim3(74, 2), 256>>>(out);       // 148 CTAs
}

// round 12
// speedup vs baseline: 1.5514x; 1.5514x over previous
#include <cuda_runtime.h>

#define BATCH 16384

typedef unsigned long long u64;
typedef unsigned int       u32;

// Scratch (device globals: allocation-free rule)
__device__ float  g_xT[64 * BATCH];     // x transposed [i][b]
__device__ float  g_hT[64 * BATCH];     // layer0 output transposed [o][b]
__device__ float4 g_dup0[4096 * 6];     // layer0 params, duplicated (w,w) pairs
__device__ float4 g_dup1[1024 * 6];     // layer1 params, duplicated pairs
__device__ float  g_b3s0[64];           // sum_i b3 per output o, layer0
__device__ float  g_b3s1[16];           // layer1

__device__ __forceinline__ u64 fma2(u64 a, u64 b, u64 c) {
    u64 d;
    asm("fma.rn.f32x2 %0, %1, %2, %3;" : "=l"(d) : "l"(a), "l"(b), "l"(c));
    return d;
}
__device__ __forceinline__ u64 pk(float a, float b) {
    return (u64)__float_as_uint(a) | ((u64)__float_as_uint(b) << 32);
}
__device__ __forceinline__ float flo(u64 v) { return __uint_as_float((u32)v); }
__device__ __forceinline__ float fhi(u64 v) { return __uint_as_float((u32)(v >> 32)); }
__device__ __forceinline__ u64 relu2(u64 v) {
    return pk(fmaxf(flo(v), 0.0f), fmaxf(fhi(v), 0.0f));
}

// Fused prep: blocks 0..19 param duplication (5120 subnets, 1 thread each),
// blocks 20..29 b3 column sums (80 warps), blocks 30..541 x transpose tiles
// (512 tiles of 32 batch x 64 i).
__global__ __launch_bounds__(256) void prep(
    const float* __restrict__ x,
    const float* __restrict__ l0W1, const float* __restrict__ l0b1,
    const float* __restrict__ l0W2, const float* __restrict__ l0b2,
    const float* __restrict__ l0W3, const float* __restrict__ l0b3,
    const float* __restrict__ l1W1, const float* __restrict__ l1b1,
    const float* __restrict__ l1W2, const float* __restrict__ l1b2,
    const float* __restrict__ l1W3, const float* __restrict__ l1b3)
{
    __shared__ float ts[64 * 33];
    int blk = blockIdx.x, tid = threadIdx.x;

    if (blk < 20) {
        int t = blk * 256 + tid;             // 0..5119
        bool isL0 = t < 4096;
        int n = isL0 ? t : t - 4096;
        const float* W1 = isL0 ? l0W1 : l1W1;
        const float* b1 = isL0 ? l0b1 : l1b1;
        const float* W2 = isL0 ? l0W2 : l1W2;
        const float* b2 = isL0 ? l0b2 : l1b2;
        const float* W3 = isL0 ? l0W3 : l1W3;
        float4* q = (isL0 ? g_dup0 : g_dup1) + (size_t)n * 6;
        float w1a = W1[2*n], w1b = W1[2*n+1];
        float b1a = b1[2*n], b1b = b1[2*n+1];
        float w200 = W2[4*n], w201 = W2[4*n+1], w210 = W2[4*n+2], w211 = W2[4*n+3];
        float b2a = b2[2*n], b2b = b2[2*n+1];
        float w3a = W3[2*n], w3b = W3[2*n+1];
        q[0] = make_float4(w1a, w1a, w1b, w1b);
        q[1] = make_float4(b1a, b1a, b1b, b1b);
        q[2] = make_float4(w200, w200, w201, w201);
        q[3] = make_float4(w210, w210, w211, w211);
        q[4] = make_float4(b2a, b2a, b2b, b2b);
        q[5] = make_float4(w3a, w3a, w3b, w3b);
    } else if (blk < 30) {
        int wg = (blk - 20) * 8 + (tid >> 5);   // 0..79
        int lane = tid & 31;
        bool isL0 = wg < 64;
        int o = isL0 ? wg : wg - 64;
        int OUT = isL0 ? 64 : 16;
        const float* b3 = isL0 ? l0b3 : l1b3;
        float s = b3[lane * OUT + o] + b3[(lane + 32) * OUT + o];
#pragma unroll
        for (int m = 16; m; m >>= 1) s += __shfl_xor_sync(0xffffffffu, s, m);
        if (lane == 0) (isL0 ? g_b3s0 : g_b3s1)[o] = s;
    } else {
        // Transpose a 32b x 64i tile of x into g_xT, fully vectorized.
        int B0 = (blk - 30) * 32;
        int brow = tid >> 3, i4 = tid & 7;       // 32 rows, 8 f4-cols
#pragma unroll
        for (int p = 0; p < 2; p++) {
            int c = (p * 8 + i4) * 4;
            float4 v = *(const float4*)&x[(size_t)(B0 + brow) * 64 + c];
            ts[(c + 0) * 33 + brow] = v.x;
            ts[(c + 1) * 33 + brow] = v.y;
            ts[(c + 2) * 33 + brow] = v.z;
            ts[(c + 3) * 33 + brow] = v.w;
        }
        __syncthreads();
#pragma unroll
        for (int p = 0; p < 2; p++) {
            int idx = p * 256 + tid;             // 0..511
            int i = idx >> 3, bq = (idx & 7) * 4;
            float4 w = make_float4(ts[i * 33 + bq],     ts[i * 33 + bq + 1],
                                   ts[i * 33 + bq + 2], ts[i * 33 + bq + 3]);
            *(float4*)&g_xT[(size_t)i * BATCH + B0 + bq] = w;
        }
    }
}

// One KAN layer. 128 threads = 4 warps; warp ol owns output column o = o0+ol
// for a 256-batch strip; lane handles 4 f32x2 streams at b, b+64, b+128,
// b+192. Identical per-warp inner loop to the R6 best (6 uniform LDS.128 +
// 4 coalesced LDG.64 per (i, 256 evals)), but the 4-column/24KB CTA shape
// gives 1024 CTAs -> single full wave (>=7 CTAs/SM) -> quantization ~1.01.
// MODE 0: g_xT -> g_hT (transposed rows). MODE 1: g_hT -> dout [b][OUT].
template <int OUT, int MODE>
__global__ __launch_bounds__(128) void kan_layer(float* __restrict__ dout)
{
    __shared__ float4 sp4[64 * 4 * 6];   // 24KB: [i][ol][6]

    int tid  = threadIdx.x;
    int lane = tid & 31;
    int ol   = tid >> 5;
    int o0   = blockIdx.y * 4;
    int o    = o0 + ol;
    int B0   = blockIdx.x * 256;
    int b    = B0 + lane * 2;

    // Stage params: per i, the 4 subnets n = i*OUT + o0..+3 are 24 contiguous
    // float4 in g_dup -> flat coalesced copy, 12 float4 per thread.
    const float4* dup = ((MODE == 0) ? g_dup0 : g_dup1);
#pragma unroll
    for (int s = tid; s < 1536; s += 128) {
        int i = s / 24;
        int r = s - i * 24;
        sp4[s] = dup[(size_t)(i * OUT + o0) * 6 + r];
    }

    float s3 = ((MODE == 0) ? g_b3s0 : g_b3s1)[o];
    __syncthreads();

    const float* src = (MODE == 0) ? g_xT : g_hT;
    const float* xr  = src + b;
    const ulonglong2* pb = ((const ulonglong2*)sp4) + ol * 6;

    u64 acc0 = pk(s3, s3), acc1 = acc0, acc2 = acc0, acc3 = acc0;

#pragma unroll 2
    for (int i = 0; i < 64; i++) {
        const ulonglong2* q = pb + i * 24;
        ulonglong2 p0 = q[0], p1 = q[1], p2 = q[2], p3 = q[3], p4 = q[4], p5 = q[5];
        const float* xi = xr + (size_t)i * BATCH;

        u64 xv, r1, r2, ga, gb;
        xv = *(const u64*)(xi);
        r1 = relu2(fma2(p0.x, xv, p1.x));
        r2 = relu2(fma2(p0.y, xv, p1.y));
        ga = relu2(fma2(p2.x, r1, fma2(p2.y, r2, p4.x)));
        gb = relu2(fma2(p3.x, r1, fma2(p3.y, r2, p4.y)));
        acc0 = fma2(p5.y, gb, fma2(p5.x, ga, acc0));

        xv = *(const u64*)(xi + 64);
        r1 = relu2(fma2(p0.x, xv, p1.x));
        r2 = relu2(fma2(p0.y, xv, p1.y));
        ga = relu2(fma2(p2.x, r1, fma2(p2.y, r2, p4.x)));
        gb = relu2(fma2(p3.x, r1, fma2(p3.y, r2, p4.y)));
        acc1 = fma2(p5.y, gb, fma2(p5.x, ga, acc1));

        xv = *(const u64*)(xi + 128);
        r1 = relu2(fma2(p0.x, xv, p1.x));
        r2 = relu2(fma2(p0.y, xv, p1.y));
        ga = relu2(fma2(p2.x, r1, fma2(p2.y, r2, p4.x)));
        gb = relu2(fma2(p3.x, r1, fma2(p3.y, r2, p4.y)));
        acc2 = fma2(p5.y, gb, fma2(p5.x, ga, acc2));

        xv = *(const u64*)(xi + 192);
        r1 = relu2(fma2(p0.x, xv, p1.x));
        r2 = relu2(fma2(p0.y, xv, p1.y));
        ga = relu2(fma2(p2.x, r1, fma2(p2.y, r2, p4.x)));
        gb = relu2(fma2(p3.x, r1, fma2(p3.y, r2, p4.y)));
        acc3 = fma2(p5.y, gb, fma2(p5.x, ga, acc3));
    }

    if (MODE == 0) {
        float* row = g_hT + (size_t)o * BATCH + b;
        *(u64*)(row)       = acc0;
        *(u64*)(row + 64)  = acc1;
        *(u64*)(row + 128) = acc2;
        *(u64*)(row + 192) = acc3;
    } else {
        dout[(size_t)(b + 0)   * OUT + o] = flo(acc0);
        dout[(size_t)(b + 1)   * OUT + o] = fhi(acc0);
        dout[(size_t)(b + 64)  * OUT + o] = flo(acc1);
        dout[(size_t)(b + 65)  * OUT + o] = fhi(acc1);
        dout[(size_t)(b + 128) * OUT + o] = flo(acc2);
        dout[(size_t)(b + 129) * OUT + o] = fhi(acc2);
        dout[(size_t)(b + 192) * OUT + o] = flo(acc3);
        dout[(size_t)(b + 193) * OUT + o] = fhi(acc3);
    }
}

extern "C" void kernel_launch(void* const* d_in, const int* in_sizes, int n_in,
                              void* d_out, int out_size)
{
    const float* x    = (const float*)d_in[0];
    const float* l0W1 = (const float*)d_in[1];
    const float* l0b1 = (const float*)d_in[2];
    const float* l0W2 = (const float*)d_in[3];
    const float* l0b2 = (const float*)d_in[4];
    const float* l0W3 = (const float*)d_in[5];
    const float* l0b3 = (const float*)d_in[6];
    const float* l1W1 = (const float*)d_in[7];
    const float* l1b1 = (const float*)d_in[8];
    const float* l1W2 = (const float*)d_in[9];
    const float* l1b2 = (const float*)d_in[10];
    const float* l1W3 = (const float*)d_in[11];
    const float* l1b3 = (const float*)d_in[12];
    float* out = (float*)d_out;

    prep<<<542, 256>>>(x, l0W1, l0b1, l0W2, l0b2, l0W3, l0b3,
                          l1W1, l1b1, l1W2, l1b2, l1W3, l1b3);
    kan_layer<64, 0><<<dim3(BATCH / 256, 16), 128>>>(nullptr);  // 1024 CTAs
    kan_layer<16, 1><<<dim3(BATCH / 256, 4),  128>>>(out);      // 256 CTAs
}